// round 10
// baseline (speedup 1.0000x reference)
#include <cuda_runtime.h>

#define N_NODES 50000
#define N_EDGES 800000
#define D 64
#define D4 (D / 4)
#define NCLS 16
#define ROW_TILES ((N_NODES + 63) / 64)     // 782
#define GATHER_NODES_PER_BLOCK 16
#define EPT 4                                // edges per thread in build kernels
#define EDGE_THREADS (N_EDGES / EPT)         // 200000

// ---------------- scratch (float4 => 16B aligned) ----------------
__device__ float2 g_dc[N_NODES];      // .x = weighted deg (init 1 = self loop), .y = count
__device__ float  g_dinv[N_NODES];
__device__ int    g_count[N_NODES];
__device__ int    g_off[N_NODES];
__device__ int    g_cursor[N_NODES];
__device__ int    g_total;
__device__ int    g_src[N_EDGES];     // CSR: source node per slot (grouped by dst)
__device__ float  g_nrm[N_EDGES];     // CSR: edge norm per slot
__device__ float4 g_h4[N_NODES * D4];
__device__ float4 g_agg4[N_NODES * D4];

// ---------------- prep: deg=1 (self loop), count=0, total=0 ----------------
__global__ void prep_kernel(float2* dc, int* total) {
    int i = blockIdx.x * blockDim.x + threadIdx.x;
    if (i < N_NODES) dc[i] = make_float2(1.0f, 0.0f);
    if (i == 0) *total = 0;
}

// ---------------- weighted degree + count: EPT edges/thread, one v2 RED each ----------------
// Front-batched loads give MLP ~ 2*EPT; atomics are independent (fire-and-forget RED).
__global__ void deg_count_kernel(const int* __restrict__ ei,
                                 const float* __restrict__ ew,
                                 float2* dc) {
    const int t = blockIdx.x * blockDim.x + threadIdx.x;
    if (t >= EDGE_THREADS) return;

    int   c[EPT];
    float w[EPT];
    #pragma unroll
    for (int k = 0; k < EPT; k++) {
        const int e = t + k * EDGE_THREADS;   // coalesced per k
        c[k] = ei[N_EDGES + e];
        w[k] = ew[e];
    }
    #pragma unroll
    for (int k = 0; k < EPT; k++) {
        asm volatile("red.global.add.v2.f32 [%0], {%1, %2};"
                     :: "l"(dc + c[k]), "f"(w[k]), "f"(1.0f) : "memory");
    }
}

// ---------------- alloc: dinv + warp-aggregated CSR slot allocation (order-free) ----------------
// Node order within the CSR slab is irrelevant (gather uses off/count only),
// so no global scan: warp-scan + one atomic per warp.
__global__ void alloc_kernel(const float2* __restrict__ dc,
                             int* __restrict__ count,
                             float* __restrict__ dinv,
                             int* __restrict__ off,
                             int* __restrict__ cursor,
                             int* __restrict__ total) {
    const int i = blockIdx.x * blockDim.x + threadIdx.x;
    const int lane = threadIdx.x & 31;

    int c = 0;
    if (i < N_NODES) {
        float2 v = dc[i];
        c = (int)v.y;                 // count is integral, exact in fp32
        dinv[i] = rsqrtf(v.x);        // deg >= 1 (self loop)
        count[i] = c;
    }

    // warp-inclusive scan of counts
    int incl = c;
    #pragma unroll
    for (int d = 1; d < 32; d <<= 1) {
        int v = __shfl_up_sync(0xFFFFFFFFu, incl, d);
        if (lane >= d) incl += v;
    }
    const int warpsum = __shfl_sync(0xFFFFFFFFu, incl, 31);

    int base = 0;
    if (lane == 31) base = atomicAdd(total, warpsum);
    base = __shfl_sync(0xFFFFFFFFu, base, 31);

    const int o = base + incl - c;   // exclusive offset
    if (i < N_NODES) { off[i] = o; cursor[i] = o; }
}

// ---------------- CSR fill: EPT edges/thread, batched loads then atomics ----------------
__global__ void fill_kernel(const int* __restrict__ ei,
                            const float* __restrict__ ew,
                            const float* __restrict__ dinv,
                            int* __restrict__ cursor,
                            int* __restrict__ src,
                            float* __restrict__ nrm) {
    const int t = blockIdx.x * blockDim.x + threadIdx.x;
    if (t >= EDGE_THREADS) return;

    int   r[EPT], c[EPT];
    float w[EPT];
    #pragma unroll
    for (int k = 0; k < EPT; k++) {
        const int e = t + k * EDGE_THREADS;
        r[k] = ei[e];
        c[k] = ei[N_EDGES + e];
        w[k] = ew[e];
    }
    float dr[EPT], dcv[EPT];
    #pragma unroll
    for (int k = 0; k < EPT; k++) {   // 2*EPT independent random gathers in flight
        dr[k]  = dinv[r[k]];
        dcv[k] = dinv[c[k]];
    }
    #pragma unroll
    for (int k = 0; k < EPT; k++) {
        const int slot = atomicAdd(&cursor[c[k]], 1);
        src[slot] = r[k];
        nrm[slot] = dr[k] * w[k] * dcv[k];
    }
}

// ---------------- register-blocked 64x64 GEMM: H = (relu?)(X) @ W ----------------
// block (64,4); 64 rows per block; thread tx owns column tx for 16 rows.
template <bool RELU_IN>
__global__ void gemm64_kernel(const float* __restrict__ X,
                              const float* __restrict__ W,
                              float* __restrict__ H) {
    __shared__ float Ws[64][64];
    __shared__ float Xs[64][64];
    const int tx = threadIdx.x;
    const int ty = threadIdx.y;
    const int tid = ty * 64 + tx;
    const int rb = blockIdx.x * 64;
    const int rows = min(64, N_NODES - rb);

    for (int i = tid; i < 64 * 64; i += 256)
        Ws[i >> 6][i & 63] = W[i];
    for (int i = tid; i < rows * 64; i += 256) {
        float v = X[rb * 64 + i];
        if (RELU_IN) v = fmaxf(v, 0.0f);
        Xs[i >> 6][i & 63] = v;
    }
    __syncthreads();

    float acc[16];
    #pragma unroll
    for (int j = 0; j < 16; j++) acc[j] = 0.0f;

    #pragma unroll
    for (int k0 = 0; k0 < 64; k0 += 4) {
        const float w0 = Ws[k0 + 0][tx];
        const float w1 = Ws[k0 + 1][tx];
        const float w2 = Ws[k0 + 2][tx];
        const float w3 = Ws[k0 + 3][tx];
        #pragma unroll
        for (int j = 0; j < 16; j++) {
            const int r = (j << 2) + ty;
            float4 xv = *reinterpret_cast<const float4*>(&Xs[r][k0]);
            acc[j] = fmaf(xv.x, w0, fmaf(xv.y, w1, fmaf(xv.z, w2, fmaf(xv.w, w3, acc[j]))));
        }
    }

    #pragma unroll
    for (int j = 0; j < 16; j++) {
        const int r = (j << 2) + ty;
        const int gr = rb + r;
        if (gr < N_NODES) H[gr * 64 + tx] = acc[j];
    }
}

// ---------------- CSR gather: agg[n] = b + dinv^2*h[n] + sum norm*h[src] ----------------
// block (16,16): x = float4 lane (16 per row), y = node within block.
// 2-way unrolled edge loop for memory-level parallelism.
__global__ void gather_kernel(const int* __restrict__ off,
                              const int* __restrict__ count,
                              const int* __restrict__ src,
                              const float* __restrict__ nrm,
                              const float* __restrict__ dinv,
                              const float* __restrict__ b,
                              const float4* __restrict__ h4,
                              float4* __restrict__ agg4) {
    const int sub = threadIdx.x;
    const int n = blockIdx.x * GATHER_NODES_PER_BLOCK + threadIdx.y;
    if (n >= N_NODES) return;

    const int beg = off[n];
    const int end = beg + count[n];

    float4 acc0 = make_float4(0.f, 0.f, 0.f, 0.f);
    float4 acc1 = make_float4(0.f, 0.f, 0.f, 0.f);
    int s = beg;
    for (; s + 1 < end; s += 2) {
        const int r0 = src[s];
        const int r1 = src[s + 1];
        const float nm0 = nrm[s];
        const float nm1 = nrm[s + 1];
        const float4 hv0 = h4[r0 * D4 + sub];
        const float4 hv1 = h4[r1 * D4 + sub];
        acc0.x = fmaf(nm0, hv0.x, acc0.x);
        acc0.y = fmaf(nm0, hv0.y, acc0.y);
        acc0.z = fmaf(nm0, hv0.z, acc0.z);
        acc0.w = fmaf(nm0, hv0.w, acc0.w);
        acc1.x = fmaf(nm1, hv1.x, acc1.x);
        acc1.y = fmaf(nm1, hv1.y, acc1.y);
        acc1.z = fmaf(nm1, hv1.z, acc1.z);
        acc1.w = fmaf(nm1, hv1.w, acc1.w);
    }
    if (s < end) {
        const int r = src[s];
        const float nm = nrm[s];
        const float4 hv = h4[r * D4 + sub];
        acc0.x = fmaf(nm, hv.x, acc0.x);
        acc0.y = fmaf(nm, hv.y, acc0.y);
        acc0.z = fmaf(nm, hv.z, acc0.z);
        acc0.w = fmaf(nm, hv.w, acc0.w);
    }

    const float di = dinv[n];
    const float d2 = di * di;
    const float4 hn = h4[n * D4 + sub];
    const float4 bv = reinterpret_cast<const float4*>(b)[sub];
    agg4[n * D4 + sub] = make_float4(acc0.x + acc1.x + fmaf(d2, hn.x, bv.x),
                                     acc0.y + acc1.y + fmaf(d2, hn.y, bv.y),
                                     acc0.z + acc1.z + fmaf(d2, hn.z, bv.z),
                                     acc0.w + acc1.w + fmaf(d2, hn.w, bv.w));
}

// ---------------- fused MLP head + sigmoid ----------------
__global__ void mlp_kernel(const float* __restrict__ A,
                           const float* __restrict__ Wm1,
                           const float* __restrict__ bm1,
                           const float* __restrict__ Wm2,
                           const float* __restrict__ bm2,
                           float* __restrict__ out) {
    __shared__ float W1s[64][64];
    __shared__ float Xs[64][64];
    __shared__ float T[64][68];
    __shared__ float W2s[64][NCLS];
    __shared__ float b1s[64];
    __shared__ float b2s[NCLS];

    const int tx = threadIdx.x;
    const int ty = threadIdx.y;
    const int tid = ty * 64 + tx;
    const int rb = blockIdx.x * 64;
    const int rows = min(64, N_NODES - rb);

    for (int i = tid; i < 64 * 64; i += 256)
        W1s[i >> 6][i & 63] = Wm1[i];
    for (int i = tid; i < 64 * NCLS; i += 256)
        W2s[i / NCLS][i % NCLS] = Wm2[i];
    if (tid < 64) b1s[tid] = bm1[tid];
    if (tid < NCLS) b2s[tid] = bm2[tid];
    for (int i = tid; i < rows * 64; i += 256)
        Xs[i >> 6][i & 63] = fmaxf(A[rb * 64 + i], 0.0f);
    __syncthreads();

    float acc[16];
    #pragma unroll
    for (int j = 0; j < 16; j++) acc[j] = b1s[tx];

    #pragma unroll
    for (int k0 = 0; k0 < 64; k0 += 4) {
        const float w0 = W1s[k0 + 0][tx];
        const float w1 = W1s[k0 + 1][tx];
        const float w2 = W1s[k0 + 2][tx];
        const float w3 = W1s[k0 + 3][tx];
        #pragma unroll
        for (int j = 0; j < 16; j++) {
            const int r = (j << 2) + ty;
            float4 xv = *reinterpret_cast<const float4*>(&Xs[r][k0]);
            acc[j] = fmaf(xv.x, w0, fmaf(xv.y, w1, fmaf(xv.z, w2, fmaf(xv.w, w3, acc[j]))));
        }
    }
    #pragma unroll
    for (int j = 0; j < 16; j++)
        T[(j << 2) + ty][tx] = fmaxf(acc[j], 0.0f);
    __syncthreads();

    const int row16 = tid >> 4;
    const int cls   = tid & 15;
    #pragma unroll
    for (int rr = 0; rr < 4; rr++) {
        const int row = rr * 16 + row16;
        const int gr = rb + row;
        float acc2 = b2s[cls];
        #pragma unroll
        for (int k = 0; k < 64; k++)
            acc2 = fmaf(T[row][k], W2s[k][cls], acc2);
        if (gr < N_NODES)
            out[gr * NCLS + cls] = 1.0f / (1.0f + __expf(-acc2));
    }
}

// ---------------- launch ----------------
extern "C" void kernel_launch(void* const* d_in, const int* in_sizes, int n_in,
                              void* d_out, int out_size) {
    const float* x    = (const float*)d_in[0];
    const int*   ei   = (const int*)d_in[1];
    const float* ew   = (const float*)d_in[2];
    const float* W1   = (const float*)d_in[3];
    const float* b1   = (const float*)d_in[4];
    const float* W2   = (const float*)d_in[5];
    const float* b2   = (const float*)d_in[6];
    const float* Wm1  = (const float*)d_in[7];
    const float* bm1  = (const float*)d_in[8];
    const float* Wm2  = (const float*)d_in[9];
    const float* bm2  = (const float*)d_in[10];
    float* out = (float*)d_out;

    float2 *p_dc;
    float *p_dinv, *p_nrm;
    int *p_count, *p_off, *p_cursor, *p_src, *p_total;
    float4 *p_h4, *p_agg4;
    cudaGetSymbolAddress((void**)&p_dc,     g_dc);
    cudaGetSymbolAddress((void**)&p_dinv,   g_dinv);
    cudaGetSymbolAddress((void**)&p_count,  g_count);
    cudaGetSymbolAddress((void**)&p_off,    g_off);
    cudaGetSymbolAddress((void**)&p_cursor, g_cursor);
    cudaGetSymbolAddress((void**)&p_total,  g_total);
    cudaGetSymbolAddress((void**)&p_src,    g_src);
    cudaGetSymbolAddress((void**)&p_nrm,    g_nrm);
    cudaGetSymbolAddress((void**)&p_h4,     g_h4);
    cudaGetSymbolAddress((void**)&p_agg4,   g_agg4);
    float* p_h   = (float*)p_h4;
    float* p_agg = (float*)p_agg4;

    const dim3 blk2d(64, 4);
    const dim3 blkg(16, GATHER_NODES_PER_BLOCK);
    const int GATHER_GRID = (N_NODES + GATHER_NODES_PER_BLOCK - 1) / GATHER_NODES_PER_BLOCK;
    const int EDGE_GRID = (EDGE_THREADS + 255) / 256;

    // CSR build (reused by both layers)
    prep_kernel<<<(N_NODES + 255) / 256, 256>>>(p_dc, p_total);
    deg_count_kernel<<<EDGE_GRID, 256>>>(ei, ew, p_dc);
    alloc_kernel<<<(N_NODES + 255) / 256, 256>>>(p_dc, p_count, p_dinv, p_off, p_cursor, p_total);
    fill_kernel<<<EDGE_GRID, 256>>>(ei, ew, p_dinv, p_cursor, p_src, p_nrm);

    // layer 1
    gemm64_kernel<false><<<ROW_TILES, blk2d>>>(x, W1, p_h);
    gather_kernel<<<GATHER_GRID, blkg>>>(p_off, p_count, p_src, p_nrm, p_dinv, b1, p_h4, p_agg4);

    // layer 2
    gemm64_kernel<true><<<ROW_TILES, blk2d>>>(p_agg, W2, p_h);
    gather_kernel<<<GATHER_GRID, blkg>>>(p_off, p_count, p_src, p_nrm, p_dinv, b2, p_h4, p_agg4);

    // MLP head + sigmoid
    mlp_kernel<<<ROW_TILES, blk2d>>>(p_agg, Wm1, bm1, Wm2, bm2, out);
}

// round 11
// speedup vs baseline: 1.0746x; 1.0746x over previous
#include <cuda_runtime.h>
#include <cuda_fp16.h>

#define N_NODES 50000
#define N_EDGES 800000
#define D 64
#define D4 (D / 4)
#define NCLS 16
#define ROW_TILES ((N_NODES + 63) / 64)     // 782
#define GATHER_NODES_PER_BLOCK 16

// ---------------- scratch ----------------
__device__ float2 g_dc[N_NODES];      // .x = weighted deg (init 1 = self loop), .y = count
__device__ float  g_dinv[N_NODES];
__device__ int    g_count[N_NODES];
__device__ int    g_off[N_NODES];
__device__ int    g_cursor[N_NODES];
__device__ int    g_total;
__device__ int    g_src[N_EDGES];     // CSR: source node per slot (grouped by dst)
__device__ float  g_nrm[N_EDGES];     // CSR: edge norm per slot
__device__ uint2  g_h2[N_NODES * 16]; // h in fp16: 64 halves = 16 uint2 (4 halves each) per row
__device__ float4 g_agg4[N_NODES * D4];

// ---------------- prep: deg=1 (self loop), count=0, total=0 ----------------
__global__ void prep_kernel(float2* dc, int* total) {
    int i = blockIdx.x * blockDim.x + threadIdx.x;
    if (i < N_NODES) dc[i] = make_float2(1.0f, 0.0f);
    if (i == 0) *total = 0;
}

// ---------------- weighted degree + count: one v2 vector RED per edge ----------------
__global__ void deg_count_kernel(const int* __restrict__ ei,
                                 const float* __restrict__ ew,
                                 float2* dc) {
    int e = blockIdx.x * blockDim.x + threadIdx.x;
    if (e < N_EDGES) {
        int c = ei[N_EDGES + e];
        float w = ew[e];
        asm volatile("red.global.add.v2.f32 [%0], {%1, %2};"
                     :: "l"(dc + c), "f"(w), "f"(1.0f) : "memory");
    }
}

// ---------------- alloc: dinv + warp-aggregated CSR slot allocation (order-free) ----------------
__global__ void alloc_kernel(const float2* __restrict__ dc,
                             int* __restrict__ count,
                             float* __restrict__ dinv,
                             int* __restrict__ off,
                             int* __restrict__ cursor,
                             int* __restrict__ total) {
    const int i = blockIdx.x * blockDim.x + threadIdx.x;
    const int lane = threadIdx.x & 31;

    int c = 0;
    if (i < N_NODES) {
        float2 v = dc[i];
        c = (int)v.y;                 // count is integral, exact in fp32
        dinv[i] = rsqrtf(v.x);        // deg >= 1 (self loop)
        count[i] = c;
    }

    int incl = c;
    #pragma unroll
    for (int d = 1; d < 32; d <<= 1) {
        int v = __shfl_up_sync(0xFFFFFFFFu, incl, d);
        if (lane >= d) incl += v;
    }
    const int warpsum = __shfl_sync(0xFFFFFFFFu, incl, 31);

    int base = 0;
    if (lane == 31) base = atomicAdd(total, warpsum);
    base = __shfl_sync(0xFFFFFFFFu, base, 31);

    const int o = base + incl - c;   // exclusive offset
    if (i < N_NODES) { off[i] = o; cursor[i] = o; }
}

// ---------------- CSR fill: slot per (dst) + norm precompute ----------------
__global__ void fill_kernel(const int* __restrict__ ei,
                            const float* __restrict__ ew,
                            const float* __restrict__ dinv,
                            int* __restrict__ cursor,
                            int* __restrict__ src,
                            float* __restrict__ nrm) {
    int e = blockIdx.x * blockDim.x + threadIdx.x;
    if (e < N_EDGES) {
        int r = ei[e];
        int c = ei[N_EDGES + e];
        float nm = dinv[r] * ew[e] * dinv[c];
        int slot = atomicAdd(&cursor[c], 1);
        src[slot] = r;
        nrm[slot] = nm;
    }
}

// ---------------- register-blocked 64x64 GEMM: Hfp16 = (relu?)(X) @ W ----------------
// block (64,4); 64 rows per block; thread tx owns column tx for 16 rows.
template <bool RELU_IN>
__global__ void gemm64_kernel(const float* __restrict__ X,
                              const float* __restrict__ W,
                              __half* __restrict__ H) {
    __shared__ float Ws[64][64];
    __shared__ float Xs[64][64];
    const int tx = threadIdx.x;
    const int ty = threadIdx.y;
    const int tid = ty * 64 + tx;
    const int rb = blockIdx.x * 64;
    const int rows = min(64, N_NODES - rb);

    for (int i = tid; i < 64 * 64; i += 256)
        Ws[i >> 6][i & 63] = W[i];
    for (int i = tid; i < rows * 64; i += 256) {
        float v = X[rb * 64 + i];
        if (RELU_IN) v = fmaxf(v, 0.0f);
        Xs[i >> 6][i & 63] = v;
    }
    __syncthreads();

    float acc[16];
    #pragma unroll
    for (int j = 0; j < 16; j++) acc[j] = 0.0f;

    #pragma unroll
    for (int k0 = 0; k0 < 64; k0 += 4) {
        const float w0 = Ws[k0 + 0][tx];
        const float w1 = Ws[k0 + 1][tx];
        const float w2 = Ws[k0 + 2][tx];
        const float w3 = Ws[k0 + 3][tx];
        #pragma unroll
        for (int j = 0; j < 16; j++) {
            const int r = (j << 2) + ty;
            float4 xv = *reinterpret_cast<const float4*>(&Xs[r][k0]);
            acc[j] = fmaf(xv.x, w0, fmaf(xv.y, w1, fmaf(xv.z, w2, fmaf(xv.w, w3, acc[j]))));
        }
    }

    #pragma unroll
    for (int j = 0; j < 16; j++) {
        const int r = (j << 2) + ty;
        const int gr = rb + r;
        if (gr < N_NODES) H[gr * 64 + tx] = __float2half(acc[j]);
    }
}

// ---------------- CSR gather: agg[n] = b + dinv^2*h[n] + sum norm*h[src] ----------------
// block (16,16): x = lane (4 halves = 8B each), y = node within block.
// 2-way unrolled edge loop for memory-level parallelism. h rows are fp16 (128B).
__global__ void gather_kernel(const int* __restrict__ off,
                              const int* __restrict__ count,
                              const int* __restrict__ src,
                              const float* __restrict__ nrm,
                              const float* __restrict__ dinv,
                              const float* __restrict__ b,
                              const uint2* __restrict__ h2,
                              float4* __restrict__ agg4) {
    const int sub = threadIdx.x;
    const int n = blockIdx.x * GATHER_NODES_PER_BLOCK + threadIdx.y;
    if (n >= N_NODES) return;

    const int beg = off[n];
    const int end = beg + count[n];

    float4 acc0 = make_float4(0.f, 0.f, 0.f, 0.f);
    float4 acc1 = make_float4(0.f, 0.f, 0.f, 0.f);
    int s = beg;
    for (; s + 1 < end; s += 2) {
        const int r0 = src[s];
        const int r1 = src[s + 1];
        const float nm0 = nrm[s];
        const float nm1 = nrm[s + 1];
        const uint2 hv0 = h2[r0 * 16 + sub];
        const uint2 hv1 = h2[r1 * 16 + sub];
        const float2 a0 = __half22float2(*reinterpret_cast<const __half2*>(&hv0.x));
        const float2 a1 = __half22float2(*reinterpret_cast<const __half2*>(&hv0.y));
        const float2 b0 = __half22float2(*reinterpret_cast<const __half2*>(&hv1.x));
        const float2 b1 = __half22float2(*reinterpret_cast<const __half2*>(&hv1.y));
        acc0.x = fmaf(nm0, a0.x, acc0.x);
        acc0.y = fmaf(nm0, a0.y, acc0.y);
        acc0.z = fmaf(nm0, a1.x, acc0.z);
        acc0.w = fmaf(nm0, a1.y, acc0.w);
        acc1.x = fmaf(nm1, b0.x, acc1.x);
        acc1.y = fmaf(nm1, b0.y, acc1.y);
        acc1.z = fmaf(nm1, b1.x, acc1.z);
        acc1.w = fmaf(nm1, b1.y, acc1.w);
    }
    if (s < end) {
        const int r = src[s];
        const float nm = nrm[s];
        const uint2 hv = h2[r * 16 + sub];
        const float2 a0 = __half22float2(*reinterpret_cast<const __half2*>(&hv.x));
        const float2 a1 = __half22float2(*reinterpret_cast<const __half2*>(&hv.y));
        acc0.x = fmaf(nm, a0.x, acc0.x);
        acc0.y = fmaf(nm, a0.y, acc0.y);
        acc0.z = fmaf(nm, a1.x, acc0.z);
        acc0.w = fmaf(nm, a1.y, acc0.w);
    }

    const float di = dinv[n];
    const float d2 = di * di;
    const uint2 hn = h2[n * 16 + sub];
    const float2 s0 = __half22float2(*reinterpret_cast<const __half2*>(&hn.x));
    const float2 s1 = __half22float2(*reinterpret_cast<const __half2*>(&hn.y));
    const float4 bv = reinterpret_cast<const float4*>(b)[sub];
    agg4[n * D4 + sub] = make_float4(acc0.x + acc1.x + fmaf(d2, s0.x, bv.x),
                                     acc0.y + acc1.y + fmaf(d2, s0.y, bv.y),
                                     acc0.z + acc1.z + fmaf(d2, s1.x, bv.z),
                                     acc0.w + acc1.w + fmaf(d2, s1.y, bv.w));
}

// ---------------- fused MLP head + sigmoid ----------------
__global__ void mlp_kernel(const float* __restrict__ A,
                           const float* __restrict__ Wm1,
                           const float* __restrict__ bm1,
                           const float* __restrict__ Wm2,
                           const float* __restrict__ bm2,
                           float* __restrict__ out) {
    __shared__ float W1s[64][64];
    __shared__ float Xs[64][64];
    __shared__ float T[64][68];
    __shared__ float W2s[64][NCLS];
    __shared__ float b1s[64];
    __shared__ float b2s[NCLS];

    const int tx = threadIdx.x;
    const int ty = threadIdx.y;
    const int tid = ty * 64 + tx;
    const int rb = blockIdx.x * 64;
    const int rows = min(64, N_NODES - rb);

    for (int i = tid; i < 64 * 64; i += 256)
        W1s[i >> 6][i & 63] = Wm1[i];
    for (int i = tid; i < 64 * NCLS; i += 256)
        W2s[i / NCLS][i % NCLS] = Wm2[i];
    if (tid < 64) b1s[tid] = bm1[tid];
    if (tid < NCLS) b2s[tid] = bm2[tid];
    for (int i = tid; i < rows * 64; i += 256)
        Xs[i >> 6][i & 63] = fmaxf(A[rb * 64 + i], 0.0f);
    __syncthreads();

    float acc[16];
    #pragma unroll
    for (int j = 0; j < 16; j++) acc[j] = b1s[tx];

    #pragma unroll
    for (int k0 = 0; k0 < 64; k0 += 4) {
        const float w0 = W1s[k0 + 0][tx];
        const float w1 = W1s[k0 + 1][tx];
        const float w2 = W1s[k0 + 2][tx];
        const float w3 = W1s[k0 + 3][tx];
        #pragma unroll
        for (int j = 0; j < 16; j++) {
            const int r = (j << 2) + ty;
            float4 xv = *reinterpret_cast<const float4*>(&Xs[r][k0]);
            acc[j] = fmaf(xv.x, w0, fmaf(xv.y, w1, fmaf(xv.z, w2, fmaf(xv.w, w3, acc[j]))));
        }
    }
    #pragma unroll
    for (int j = 0; j < 16; j++)
        T[(j << 2) + ty][tx] = fmaxf(acc[j], 0.0f);
    __syncthreads();

    const int row16 = tid >> 4;
    const int cls   = tid & 15;
    #pragma unroll
    for (int rr = 0; rr < 4; rr++) {
        const int row = rr * 16 + row16;
        const int gr = rb + row;
        float acc2 = b2s[cls];
        #pragma unroll
        for (int k = 0; k < 64; k++)
            acc2 = fmaf(T[row][k], W2s[k][cls], acc2);
        if (gr < N_NODES)
            out[gr * NCLS + cls] = 1.0f / (1.0f + __expf(-acc2));
    }
}

// ---------------- launch ----------------
extern "C" void kernel_launch(void* const* d_in, const int* in_sizes, int n_in,
                              void* d_out, int out_size) {
    const float* x    = (const float*)d_in[0];
    const int*   ei   = (const int*)d_in[1];
    const float* ew   = (const float*)d_in[2];
    const float* W1   = (const float*)d_in[3];
    const float* b1   = (const float*)d_in[4];
    const float* W2   = (const float*)d_in[5];
    const float* b2   = (const float*)d_in[6];
    const float* Wm1  = (const float*)d_in[7];
    const float* bm1  = (const float*)d_in[8];
    const float* Wm2  = (const float*)d_in[9];
    const float* bm2  = (const float*)d_in[10];
    float* out = (float*)d_out;

    float2 *p_dc;
    float *p_dinv, *p_nrm;
    int *p_count, *p_off, *p_cursor, *p_src, *p_total;
    uint2 *p_h2;
    float4 *p_agg4;
    cudaGetSymbolAddress((void**)&p_dc,     g_dc);
    cudaGetSymbolAddress((void**)&p_dinv,   g_dinv);
    cudaGetSymbolAddress((void**)&p_count,  g_count);
    cudaGetSymbolAddress((void**)&p_off,    g_off);
    cudaGetSymbolAddress((void**)&p_cursor, g_cursor);
    cudaGetSymbolAddress((void**)&p_total,  g_total);
    cudaGetSymbolAddress((void**)&p_src,    g_src);
    cudaGetSymbolAddress((void**)&p_nrm,    g_nrm);
    cudaGetSymbolAddress((void**)&p_h2,     g_h2);
    cudaGetSymbolAddress((void**)&p_agg4,   g_agg4);
    __half* p_h   = (__half*)p_h2;
    float*  p_agg = (float*)p_agg4;

    const dim3 blk2d(64, 4);
    const dim3 blkg(16, GATHER_NODES_PER_BLOCK);
    const int GATHER_GRID = (N_NODES + GATHER_NODES_PER_BLOCK - 1) / GATHER_NODES_PER_BLOCK;

    // CSR build (reused by both layers)
    prep_kernel<<<(N_NODES + 255) / 256, 256>>>(p_dc, p_total);
    deg_count_kernel<<<(N_EDGES + 255) / 256, 256>>>(ei, ew, p_dc);
    alloc_kernel<<<(N_NODES + 255) / 256, 256>>>(p_dc, p_count, p_dinv, p_off, p_cursor, p_total);
    fill_kernel<<<(N_EDGES + 255) / 256, 256>>>(ei, ew, p_dinv, p_cursor, p_src, p_nrm);

    // layer 1
    gemm64_kernel<false><<<ROW_TILES, blk2d>>>(x, W1, p_h);
    gather_kernel<<<GATHER_GRID, blkg>>>(p_off, p_count, p_src, p_nrm, p_dinv, b1, p_h2, p_agg4);

    // layer 2
    gemm64_kernel<true><<<ROW_TILES, blk2d>>>(p_agg, W2, p_h);
    gather_kernel<<<GATHER_GRID, blkg>>>(p_off, p_count, p_src, p_nrm, p_dinv, b2, p_h2, p_agg4);

    // MLP head + sigmoid
    mlp_kernel<<<ROW_TILES, blk2d>>>(p_agg, Wm1, bm1, Wm2, bm2, out);
}